// round 4
// baseline (speedup 1.0000x reference)
#include <cuda_runtime.h>
#include <math.h>

#define B 64
#define T 512
#define F 512
#define H 1024
#define G4 4096   // 4*H
#define NBLK 128  // persistent blocks (must all be co-resident; 128 <= 148 SMs)

// ---------------- scratch (device globals; no allocations) ----------------
// Precomputed layer-0 input gates (+biases): layout [t][b][4H]
__device__ float g_pre[(size_t)T * B * G4];          // 512 MB
// Recurrent state, TRANSPOSED layout [h][b]; ping-pong by t parity.
__device__ float g_h0A[H * B];
__device__ float g_h0B[H * B];
__device__ float g_h1A[H * B];
__device__ float g_h1B[H * B];
__device__ float g_c0[H * B];
__device__ float g_c1[H * B];
// grid barrier state
__device__ unsigned g_barCnt;
__device__ unsigned g_barGen;

// ---------------- init ----------------
__global__ void init_state() {
    int i = blockIdx.x * blockDim.x + threadIdx.x;
    if (i < H * B) {
        g_h0A[i] = 0.f; g_h1A[i] = 0.f;
        g_c0[i]  = 0.f; g_c1[i]  = 0.f;
    }
    if (i == 0) { g_barCnt = 0u; g_barGen = 0u; }
}

// ---------------- precompute: g_pre = x @ Wi0^T + (bi0+bh0) ----------------
// M = B*T = 32768 (row r = b*T+t), N = 4096, K = 512.
// Block tile 128x64, BK=16, 256 threads, thread tile 8x4.
__global__ void precompute_kernel(const float* __restrict__ x,
                                  const float* __restrict__ Wi,
                                  const float* __restrict__ bi,
                                  const float* __restrict__ bh) {
    __shared__ float xs[16][132];   // [k][m], padded
    __shared__ float ws[16][68];    // [k][n], padded

    const int tid = threadIdx.x;
    const int tx  = tid & 15;          // n group
    const int ty  = tid >> 4;          // m group
    const int n0  = tx * 4;
    const int m0  = ty * 8;
    const int rBase = blockIdx.y * 128;
    const int nBase = blockIdx.x * 64;

    float acc[8][4];
#pragma unroll
    for (int i = 0; i < 8; i++)
#pragma unroll
        for (int j = 0; j < 4; j++) acc[i][j] = 0.f;

    for (int kb = 0; kb < F; kb += 16) {
#pragma unroll
        for (int it = 0; it < 2; it++) {
            int i = tid + it * 256;
            int m = i >> 2, kq = i & 3;
            float4 v = *(const float4*)&x[(size_t)(rBase + m) * F + kb + kq * 4];
            xs[kq * 4 + 0][m] = v.x; xs[kq * 4 + 1][m] = v.y;
            xs[kq * 4 + 2][m] = v.z; xs[kq * 4 + 3][m] = v.w;
        }
        {
            int n = tid >> 2, kq = tid & 3;
            float4 v = *(const float4*)&Wi[(size_t)(nBase + n) * F + kb + kq * 4];
            ws[kq * 4 + 0][n] = v.x; ws[kq * 4 + 1][n] = v.y;
            ws[kq * 4 + 2][n] = v.z; ws[kq * 4 + 3][n] = v.w;
        }
        __syncthreads();
#pragma unroll
        for (int k = 0; k < 16; k++) {
            float4 a0 = *(const float4*)&xs[k][m0];
            float4 a1 = *(const float4*)&xs[k][m0 + 4];
            float4 b4 = *(const float4*)&ws[k][n0];
            float am[8] = {a0.x, a0.y, a0.z, a0.w, a1.x, a1.y, a1.z, a1.w};
            float bn[4] = {b4.x, b4.y, b4.z, b4.w};
#pragma unroll
            for (int i = 0; i < 8; i++)
#pragma unroll
                for (int j = 0; j < 4; j++)
                    acc[i][j] = fmaf(am[i], bn[j], acc[i][j]);
        }
        __syncthreads();
    }

    float bias[4];
#pragma unroll
    for (int j = 0; j < 4; j++) bias[j] = bi[nBase + n0 + j] + bh[nBase + n0 + j];

#pragma unroll
    for (int i = 0; i < 8; i++) {
        int r = rBase + m0 + i;
        int b = r / T;
        int t = r - b * T;
        float4 v;
        v.x = acc[i][0] + bias[0];
        v.y = acc[i][1] + bias[1];
        v.z = acc[i][2] + bias[2];
        v.w = acc[i][3] + bias[3];
        *(float4*)&g_pre[((size_t)t * B + b) * G4 + nBase + n0] = v;
    }
}

// ---------------- grid barrier ----------------
__device__ __forceinline__ void grid_sync() {
    __threadfence();            // make this thread's global writes visible chip-wide
    __syncthreads();
    if (threadIdx.x == 0) {
        unsigned gen = *(volatile unsigned*)&g_barGen;
        unsigned a = atomicAdd(&g_barCnt, 1u);
        if (a == NBLK - 1) {
            g_barCnt = 0u;
            __threadfence();
            atomicAdd(&g_barGen, 1u);
        } else {
            while (*(volatile unsigned*)&g_barGen == gen) { }
        }
    }
    __syncthreads();
}

// ---------------- GEMM-accumulate helper ----------------
// acc[m] += sum_k hin[k][m] * W[j][k]. hin is [H][B] transposed state (read
// via __ldcg: written by other blocks, L1 not coherent). W is [4H][H].
// 256 threads; c = tid&31 -> (q = c>>3 gate, n = c&7 col); mg = tid>>5 -> 8 rows.
__device__ __forceinline__ void gemm_accum(const float* __restrict__ hin,
                                           const float* __restrict__ W,
                                           float acc[8],
                                           int nBase, int c, int m0, int tid,
                                           float hs[32][64], float ws[32][33]) {
    for (int kb = 0; kb < H; kb += 32) {
        __syncthreads();
#pragma unroll
        for (int it = 0; it < 8; it++) {
            int i = tid + it * 256;
            ((float*)hs)[i] = __ldcg(&hin[kb * 64 + i]);
        }
#pragma unroll
        for (int it = 0; it < 4; it++) {
            int i = tid + it * 256;
            int row = i >> 5, kk = i & 31;
            int jr = (row >> 3) * H + nBase + (row & 7);
            ws[kk][row] = W[(size_t)jr * H + kb + kk];
        }
        __syncthreads();
#pragma unroll
        for (int kk = 0; kk < 32; kk++) {
            float w = ws[kk][c];
            float4 ha = *(const float4*)&hs[kk][m0];
            float4 hb = *(const float4*)&hs[kk][m0 + 4];
            acc[0] = fmaf(ha.x, w, acc[0]);
            acc[1] = fmaf(ha.y, w, acc[1]);
            acc[2] = fmaf(ha.z, w, acc[2]);
            acc[3] = fmaf(ha.w, w, acc[3]);
            acc[4] = fmaf(hb.x, w, acc[4]);
            acc[5] = fmaf(hb.y, w, acc[5]);
            acc[6] = fmaf(hb.z, w, acc[6]);
            acc[7] = fmaf(hb.w, w, acc[7]);
        }
    }
}

__device__ __forceinline__ float sigmoidf_(float v) {
    return 1.f / (1.f + expf(-v));
}

// ---------------- persistent LSTM kernel ----------------
// Iteration it runs layer0(t=it) and layer1(t=it-1) back-to-back in each block
// (they touch disjoint buffers), then one grid barrier. 513 iterations total.
__global__ void __launch_bounds__(256, 1)
lstm_persistent(const float* __restrict__ Wh0,
                const float* __restrict__ Wi1,
                const float* __restrict__ Wh1,
                const float* __restrict__ bi1,
                const float* __restrict__ bh1,
                float* __restrict__ out) {
    __shared__ float hs[32][64];
    __shared__ float ws[32][33];
    __shared__ float sg[32][65];

    const int tid = threadIdx.x;
    const int c   = tid & 31;
    const int mg  = tid >> 5;
    const int m0  = mg * 8;
    const int nBase = blockIdx.x * 8;
    const int q = c >> 3, n = c & 7;
    const int j = q * H + nBase + n;

    const float bsum1 = bi1[j] + bh1[j];   // layer-1 bias, fixed per thread

    for (int it = 0; it <= T; it++) {
        // ---- layer 0, t = it ----
        if (it < T) {
            const int t = it;
            const float* hin  = (t & 1) ? g_h0B : g_h0A;
            float*       hout = (t & 1) ? g_h0A : g_h0B;
            const float* pre = &g_pre[(size_t)t * B * G4];

            float acc[8];
#pragma unroll
            for (int i = 0; i < 8; i++) acc[i] = pre[(size_t)(m0 + i) * G4 + j];

            gemm_accum(hin, Wh0, acc, nBase, c, m0, tid, hs, ws);

#pragma unroll
            for (int i = 0; i < 8; i++) sg[c][m0 + i] = acc[i];
            __syncthreads();

#pragma unroll
            for (int e = 0; e < 2; e++) {
                int idx = tid + e * 256;
                int nn = idx >> 6, m = idx & 63;
                float iv = sg[0 * 8 + nn][m];
                float fv = sg[1 * 8 + nn][m];
                float gv = sg[2 * 8 + nn][m];
                float ov = sg[3 * 8 + nn][m];
                int gidx = (nBase + nn) * 64 + m;
                float cP = g_c0[gidx];
                float cN = sigmoidf_(fv) * cP + sigmoidf_(iv) * tanhf(gv);
                float hN = sigmoidf_(ov) * tanhf(cN);
                g_c0[gidx] = cN;
                hout[gidx] = hN;
            }
        }

        // ---- layer 1, t = it-1 (reads h0 written last iteration) ----
        if (it > 0) {
            const int t = it - 1;
            const float* h0new = (t & 1) ? g_h0A : g_h0B;
            const float* h1in  = (t & 1) ? g_h1B : g_h1A;
            float*       h1out = (t & 1) ? g_h1A : g_h1B;

            float acc[8];
#pragma unroll
            for (int i = 0; i < 8; i++) acc[i] = bsum1;

            gemm_accum(h0new, Wi1, acc, nBase, c, m0, tid, hs, ws);
            gemm_accum(h1in,  Wh1, acc, nBase, c, m0, tid, hs, ws);

#pragma unroll
            for (int i = 0; i < 8; i++) sg[c][m0 + i] = acc[i];
            __syncthreads();

#pragma unroll
            for (int e = 0; e < 2; e++) {
                int idx = tid + e * 256;
                int nn = idx >> 6, m = idx & 63;
                float iv = sg[0 * 8 + nn][m];
                float fv = sg[1 * 8 + nn][m];
                float gv = sg[2 * 8 + nn][m];
                float ov = sg[3 * 8 + nn][m];
                int nGlob = nBase + nn;
                int gidx = nGlob * 64 + m;
                float cP = g_c1[gidx];
                float cN = sigmoidf_(fv) * cP + sigmoidf_(iv) * tanhf(gv);
                float hN = sigmoidf_(ov) * tanhf(cN);
                g_c1[gidx] = cN;
                h1out[gidx] = hN;
                out[((size_t)m * T + t) * H + nGlob] = hN;   // out[b][t][h]
            }
        }

        if (it < T) grid_sync();   // last iteration's tail only uses own-block data
    }

    // ---- finals: hT [2,B,H] then cT [2,B,H]. T even -> final h buffers are 'A'.
    // This block wrote its own columns' state; no cross-block reads needed.
    {
        size_t off = (size_t)B * T * H;
        size_t BH = (size_t)B * H;
#pragma unroll
        for (int e = 0; e < 2; e++) {
            int idx = tid + e * 256;
            int nn = idx >> 6, m = idx & 63;
            int hIdx = nBase + nn;
            int gidx = hIdx * 64 + m;
            size_t p = (size_t)m * H + hIdx;
            out[off + p]              = g_h0A[gidx];
            out[off + BH + p]         = g_h1A[gidx];
            out[off + 2 * BH + p]     = g_c0[gidx];
            out[off + 3 * BH + p]     = g_c1[gidx];
        }
    }
}

// ---------------- launch ----------------
extern "C" void kernel_launch(void* const* d_in, const int* in_sizes, int n_in,
                              void* d_out, int out_size) {
    const float* x   = (const float*)d_in[0];
    const float* Wi0 = (const float*)d_in[1];
    const float* Wh0 = (const float*)d_in[2];
    const float* bi0 = (const float*)d_in[3];
    const float* bh0 = (const float*)d_in[4];
    const float* Wi1 = (const float*)d_in[5];
    const float* Wh1 = (const float*)d_in[6];
    const float* bi1 = (const float*)d_in[7];
    const float* bh1 = (const float*)d_in[8];
    float* out = (float*)d_out;

    init_state<<<(H * B + 255) / 256, 256>>>();
    precompute_kernel<<<dim3(G4 / 64, (B * T) / 128), 256>>>(x, Wi0, bi0, bh0);
    lstm_persistent<<<NBLK, 256>>>(Wh0, Wi1, Wh1, bi1, bh1, out);
}

// round 6
// speedup vs baseline: 2.1965x; 2.1965x over previous
#include <cuda_runtime.h>
#include <math.h>
#include <stdint.h>

#define B 64
#define T 512
#define F 512
#define H 1024
#define G4 4096   // 4*H
#define NBLK 64   // persistent blocks (all co-resident; 64 <= 148 SMs)

// ---------------- scratch (device globals; no allocations) ----------------
// Precomputed layer-0 input gates (+biases): layout [t][j][b]  (b fastest!)
__device__ float g_pre[(size_t)T * G4 * B];          // 512 MB
// tf32-rounded (RNA) weight copies, same layout as originals [4H][H]
__device__ float g_Wh0r[(size_t)G4 * H];
__device__ float g_Wi1r[(size_t)G4 * H];
__device__ float g_Wh1r[(size_t)G4 * H];
// Recurrent state, TRANSPOSED layout [h][b]; ping-pong by t parity.
// h buffers hold tf32-ROUNDED values (exact MMA inputs). c is full fp32.
__device__ float g_h0A[H * B];
__device__ float g_h0B[H * B];
__device__ float g_h1A[H * B];
__device__ float g_h1B[H * B];
__device__ float g_c0[H * B];
__device__ float g_c1[H * B];
// Full-precision final h (captured at t = T-1 for hT output)
__device__ float g_h0F[H * B];
__device__ float g_h1F[H * B];
// grid barrier state
__device__ unsigned g_barCnt;
__device__ unsigned g_barGen;

// ---------------- small helpers ----------------
__device__ __forceinline__ float to_tf32(float x) {
    uint32_t u;
    asm("cvt.rna.tf32.f32 %0, %1;" : "=r"(u) : "f"(x));
    return __uint_as_float(u);
}
__device__ __forceinline__ float sigmoidf_(float v) {
    return 1.f / (1.f + expf(-v));
}
__device__ __forceinline__ void cp16(void* sdst, const void* gsrc) {
    uint32_t s = (uint32_t)__cvta_generic_to_shared(sdst);
    asm volatile("cp.async.cg.shared.global [%0], [%1], 16;\n" :: "r"(s), "l"(gsrc));
}
__device__ __forceinline__ void cp_commit() {
    asm volatile("cp.async.commit_group;\n");
}
template <int N> __device__ __forceinline__ void cp_wait() {
    asm volatile("cp.async.wait_group %0;\n" :: "n"(N));
}
__device__ __forceinline__ void mma_tf32(float c[4],
                                         uint32_t a0, uint32_t a1, uint32_t a2, uint32_t a3,
                                         uint32_t b0, uint32_t b1) {
    asm volatile(
        "mma.sync.aligned.m16n8k8.row.col.f32.tf32.tf32.f32 "
        "{%0,%1,%2,%3}, {%4,%5,%6,%7}, {%8,%9}, {%0,%1,%2,%3};\n"
        : "+f"(c[0]), "+f"(c[1]), "+f"(c[2]), "+f"(c[3])
        : "r"(a0), "r"(a1), "r"(a2), "r"(a3), "r"(b0), "r"(b1));
}

// ---------------- init kernels ----------------
__global__ void init_state() {
    int i = blockIdx.x * blockDim.x + threadIdx.x;
    if (i < H * B) {
        g_h0A[i] = 0.f; g_h0B[i] = 0.f;
        g_h1A[i] = 0.f; g_h1B[i] = 0.f;
        g_c0[i]  = 0.f; g_c1[i]  = 0.f;
    }
    if (i == 0) { g_barCnt = 0u; g_barGen = 0u; }
}

__global__ void round_weights(const float* __restrict__ Wh0,
                              const float* __restrict__ Wi1,
                              const float* __restrict__ Wh1) {
    size_t i = (size_t)blockIdx.x * blockDim.x + threadIdx.x;
    if (i < (size_t)G4 * H) {
        g_Wh0r[i] = to_tf32(Wh0[i]);
        g_Wi1r[i] = to_tf32(Wi1[i]);
        g_Wh1r[i] = to_tf32(Wh1[i]);
    }
}

// ---------------- precompute: g_pre[t][j][b] = x @ Wi0^T + (bi0+bh0) ------
// Rows r' = t*B + b (b = r'&63, t = r'>>6). fp32 FFMA (exact).
__global__ void precompute_kernel(const float* __restrict__ x,
                                  const float* __restrict__ Wi,
                                  const float* __restrict__ bi,
                                  const float* __restrict__ bh) {
    __shared__ float xs[16][132];    // [k][m], padded
    __shared__ float ws[16][68];     // [k][n], padded
    __shared__ float sgp[128][65];   // result staging for transposed store

    const int tid = threadIdx.x;
    const int tx  = tid & 15;
    const int ty  = tid >> 4;
    const int n0  = tx * 4;
    const int m0  = ty * 8;
    const int rBase = blockIdx.y * 128;
    const int nBase = blockIdx.x * 64;

    float acc[8][4];
#pragma unroll
    for (int i = 0; i < 8; i++)
#pragma unroll
        for (int j = 0; j < 4; j++) acc[i][j] = 0.f;

    for (int kb = 0; kb < F; kb += 16) {
#pragma unroll
        for (int it = 0; it < 2; it++) {
            int i = tid + it * 256;
            int m = i >> 2, kq = i & 3;
            int b = m & 63, tIdx = (rBase >> 6) + (m >> 6);
            float4 v = *(const float4*)&x[((size_t)b * T + tIdx) * F + kb + kq * 4];
            xs[kq * 4 + 0][m] = v.x; xs[kq * 4 + 1][m] = v.y;
            xs[kq * 4 + 2][m] = v.z; xs[kq * 4 + 3][m] = v.w;
        }
        {
            int n = tid >> 2, kq = tid & 3;
            float4 v = *(const float4*)&Wi[(size_t)(nBase + n) * F + kb + kq * 4];
            ws[kq * 4 + 0][n] = v.x; ws[kq * 4 + 1][n] = v.y;
            ws[kq * 4 + 2][n] = v.z; ws[kq * 4 + 3][n] = v.w;
        }
        __syncthreads();
#pragma unroll
        for (int k = 0; k < 16; k++) {
            float4 a0 = *(const float4*)&xs[k][m0];
            float4 a1 = *(const float4*)&xs[k][m0 + 4];
            float4 b4 = *(const float4*)&ws[k][n0];
            float am[8] = {a0.x, a0.y, a0.z, a0.w, a1.x, a1.y, a1.z, a1.w};
            float bn[4] = {b4.x, b4.y, b4.z, b4.w};
#pragma unroll
            for (int i = 0; i < 8; i++)
#pragma unroll
                for (int j = 0; j < 4; j++)
                    acc[i][j] = fmaf(am[i], bn[j], acc[i][j]);
        }
        __syncthreads();
    }

    float bias[4];
#pragma unroll
    for (int j = 0; j < 4; j++) bias[j] = bi[nBase + n0 + j] + bh[nBase + n0 + j];

    // stage into smem [m][n], then store transposed-coalesced
#pragma unroll
    for (int i = 0; i < 8; i++)
#pragma unroll
        for (int j = 0; j < 4; j++)
            sgp[m0 + i][n0 + j] = acc[i][j] + bias[j];
    __syncthreads();

#pragma unroll
    for (int rep = 0; rep < 32; rep++) {
        int flat = rep * 256 + tid;          // [0, 8192)
        int b = flat & 63;
        int col = flat >> 6;                 // [0, 128)
        int colIdx = col & 63;
        int tHalf = col >> 6;
        int m = tHalf * 64 + b;
        int tIdx = (rBase >> 6) + tHalf;
        g_pre[((size_t)tIdx * G4 + nBase + colIdx) * 64 + b] = sgp[m][colIdx];
    }
}

// ---------------- grid barrier ----------------
__device__ __forceinline__ void grid_sync() {
    __threadfence();
    __syncthreads();
    if (threadIdx.x == 0) {
        unsigned gen = *(volatile unsigned*)&g_barGen;
        unsigned a = atomicAdd(&g_barCnt, 1u);
        if (a == NBLK - 1) {
            g_barCnt = 0u;
            __threadfence();
            atomicAdd(&g_barGen, 1u);
        } else {
            while (*(volatile unsigned*)&g_barGen == gen) { }
        }
    }
    __syncthreads();
}

// ---------------- tf32 MMA GEMM over one K=1024 source ----------------
// Block computes C[64 m][64 n] += A[64 m][1024 k] * W[64 n][1024 k]^T
// A global layout: [k][64 m] (the transposed h state). W rounded, [4H][H],
// block rows j = (r>>4)*H + hBase + (r&15), r in [0,64).
// smem: hs[2][64][72] ([k][m]), ws[2][64][68] ([n][k]), cp.async double-buffered.
#define HS_STR 72
#define WS_STR 68
#define HS_BUF (64 * HS_STR)
#define WS_BUF (64 * WS_STR)

__device__ __forceinline__ void gemm_prefetch(const float* __restrict__ A,
                                              const float* __restrict__ Wr,
                                              float* hsb, float* wsb,
                                              int c, int buf, int hBase, int tid) {
    float* hp = hsb + buf * HS_BUF;
    float* wp = wsb + buf * WS_BUF;
#pragma unroll
    for (int it = 0; it < 4; it++) {
        int i = tid + it * 256;
        int k = i >> 4, mq = i & 15;
        cp16(&hp[k * HS_STR + mq * 4], A + (size_t)(c * 64 + k) * 64 + mq * 4);
    }
#pragma unroll
    for (int it = 0; it < 4; it++) {
        int i = tid + it * 256;
        int r = i >> 4, kq = i & 15;
        const float* src = Wr + (size_t)((r >> 4) * H + hBase + (r & 15)) * H + c * 64 + kq * 4;
        cp16(&wp[r * WS_STR + kq * 4], src);
    }
    cp_commit();
}

__device__ __forceinline__ void gemm_compute(const float* hsb, const float* wsb,
                                             int buf, float acc[4][4],
                                             int lane, int warp) {
    const float* hp = hsb + buf * HS_BUF;
    const float* wp = wsb + buf * WS_BUF;
    const int g  = lane >> 2;
    const int tg = lane & 3;
    const int mB = (warp & 3) * 16;
    const int nB = (warp >> 2) * 32;
#pragma unroll
    for (int k8 = 0; k8 < 8; k8++) {
        int k0 = k8 * 8;
        uint32_t a0 = __float_as_uint(hp[(k0 + tg) * HS_STR + mB + g]);
        uint32_t a1 = __float_as_uint(hp[(k0 + tg) * HS_STR + mB + g + 8]);
        uint32_t a2 = __float_as_uint(hp[(k0 + tg + 4) * HS_STR + mB + g]);
        uint32_t a3 = __float_as_uint(hp[(k0 + tg + 4) * HS_STR + mB + g + 8]);
#pragma unroll
        for (int ni = 0; ni < 4; ni++) {
            uint32_t b0 = __float_as_uint(wp[(nB + ni * 8 + g) * WS_STR + k0 + tg]);
            uint32_t b1 = __float_as_uint(wp[(nB + ni * 8 + g) * WS_STR + k0 + tg + 4]);
            mma_tf32(acc[ni], a0, a1, a2, a3, b0, b1);
        }
    }
}

__device__ __forceinline__ void gemm_run(const float* __restrict__ A,
                                         const float* __restrict__ Wr,
                                         float* hsb, float* wsb,
                                         float acc[4][4],
                                         int hBase, int tid, int lane, int warp) {
    gemm_prefetch(A, Wr, hsb, wsb, 0, 0, hBase, tid);
#pragma unroll 1
    for (int c = 0; c < 16; c++) {
        if (c < 15) {
            gemm_prefetch(A, Wr, hsb, wsb, c + 1, (c + 1) & 1, hBase, tid);
            cp_wait<1>();
        } else {
            cp_wait<0>();
        }
        __syncthreads();
        gemm_compute(hsb, wsb, c & 1, acc, lane, warp);
        __syncthreads();
    }
}

// ---------------- persistent LSTM kernel ----------------
// 64 blocks; block owns 16 h-cols (hBase = blockIdx.x*16) x 4 gates = 64 W rows.
// Iteration it: layer0(t=it) and layer1(t=it-1), one grid barrier.
__global__ void __launch_bounds__(256, 1)
lstm_persistent(const float* __restrict__ bi1,
                const float* __restrict__ bh1,
                float* __restrict__ out) {
    extern __shared__ float smem[];
    float* hsb = smem;                       // 2*64*72
    float* wsb = hsb + 2 * HS_BUF;           // 2*64*68
    float* sg  = wsb + 2 * WS_BUF;           // 64*65

    const int tid  = threadIdx.x;
    const int lane = tid & 31;
    const int warp = tid >> 5;
    const int hBase = blockIdx.x * 16;
    const int g  = lane >> 2;
    const int tg = lane & 3;
    const int mB = (warp & 3) * 16;
    const int nB = (warp >> 2) * 32;

    // preload layer-1 biases for this thread's epilogue cells: n_e = (tid>>6) + e*4
    float bs1[4][4];
#pragma unroll
    for (int e = 0; e < 4; e++) {
        int n = (tid >> 6) + e * 4;
#pragma unroll
        for (int q = 0; q < 4; q++) {
            int j = q * H + hBase + n;
            bs1[e][q] = bi1[j] + bh1[j];
        }
    }

    for (int it = 0; it <= T; it++) {
        // ---- layer 0, t = it ----
        if (it < T) {
            const int t = it;
            const float* hin  = (t & 1) ? g_h0B : g_h0A;
            float*       hout = (t & 1) ? g_h0A : g_h0B;

            float acc[4][4];
#pragma unroll
            for (int i = 0; i < 4; i++)
#pragma unroll
                for (int j = 0; j < 4; j++) acc[i][j] = 0.f;

            gemm_run(hin, g_Wh0r, hsb, wsb, acc, hBase, tid, lane, warp);

            // stage result to sg[m][col], col = q*16 + n
#pragma unroll
            for (int ni = 0; ni < 4; ni++) {
                int col = nB + ni * 8 + 2 * tg;
                sg[(mB + g) * 65 + col]         = acc[ni][0];
                sg[(mB + g) * 65 + col + 1]     = acc[ni][1];
                sg[(mB + g + 8) * 65 + col]     = acc[ni][2];
                sg[(mB + g + 8) * 65 + col + 1] = acc[ni][3];
            }
            __syncthreads();

            const float* pre = &g_pre[(size_t)t * G4 * 64];
#pragma unroll
            for (int e = 0; e < 4; e++) {
                int idx = tid + e * 256;
                int n = idx >> 6, m = idx & 63;
                size_t pb = (size_t)(hBase + n) * 64 + m;
                float iv = sg[m * 65 + n]      + pre[pb];
                float fv = sg[m * 65 + 16 + n] + pre[pb + (size_t)H * 64];
                float gv = sg[m * 65 + 32 + n] + pre[pb + 2 * (size_t)H * 64];
                float ov = sg[m * 65 + 48 + n] + pre[pb + 3 * (size_t)H * 64];
                int gidx = (hBase + n) * 64 + m;
                float cP = g_c0[gidx];
                float cN = sigmoidf_(fv) * cP + sigmoidf_(iv) * tanhf(gv);
                float hN = sigmoidf_(ov) * tanhf(cN);
                g_c0[gidx] = cN;
                hout[gidx] = to_tf32(hN);
                if (t == T - 1) g_h0F[gidx] = hN;
            }
            __syncthreads();
        }

        // ---- layer 1, t = it-1 ----
        if (it > 0) {
            const int t = it - 1;
            const float* h0new = (t & 1) ? g_h0A : g_h0B;
            const float* h1in  = (t & 1) ? g_h1B : g_h1A;
            float*       h1out = (t & 1) ? g_h1A : g_h1B;

            float acc[4][4];
#pragma unroll
            for (int i = 0; i < 4; i++)
#pragma unroll
                for (int j = 0; j < 4; j++) acc[i][j] = 0.f;

            gemm_run(h0new, g_Wi1r, hsb, wsb, acc, hBase, tid, lane, warp);
            gemm_run(h1in,  g_Wh1r, hsb, wsb, acc, hBase, tid, lane, warp);

#pragma unroll
            for (int ni = 0; ni < 4; ni++) {
                int col = nB + ni * 8 + 2 * tg;
                sg[(mB + g) * 65 + col]         = acc[ni][0];
                sg[(mB + g) * 65 + col + 1]     = acc[ni][1];
                sg[(mB + g + 8) * 65 + col]     = acc[ni][2];
                sg[(mB + g + 8) * 65 + col + 1] = acc[ni][3];
            }
            __syncthreads();

#pragma unroll
            for (int e = 0; e < 4; e++) {
                int idx = tid + e * 256;
                int n = idx >> 6, m = idx & 63;
                float iv = sg[m * 65 + n]      + bs1[e][0];
                float fv = sg[m * 65 + 16 + n] + bs1[e][1];
                float gv = sg[m * 65 + 32 + n] + bs1[e][2];
                float ov = sg[m * 65 + 48 + n] + bs1[e][3];
                int gidx = (hBase + n) * 64 + m;
                float cP = g_c1[gidx];
                float cN = sigmoidf_(fv) * cP + sigmoidf_(iv) * tanhf(gv);
                float hN = sigmoidf_(ov) * tanhf(cN);
                g_c1[gidx] = cN;
                h1out[gidx] = to_tf32(hN);
                if (t == T - 1) g_h1F[gidx] = hN;
                out[((size_t)m * T + t) * H + hBase + n] = hN;   // out[b][t][h]
            }
            __syncthreads();
        }

        if (it < T) grid_sync();
    }

    // ---- finals: hT [2,B,H] then cT [2,B,H]. Own columns only. ----
    {
        size_t off = (size_t)B * T * H;
        size_t BH = (size_t)B * H;
#pragma unroll
        for (int e = 0; e < 4; e++) {
            int idx = tid + e * 256;
            int n = idx >> 6, m = idx & 63;
            int hIdx = hBase + n;
            int gidx = hIdx * 64 + m;
            size_t p = (size_t)m * H + hIdx;
            out[off + p]          = g_h0F[gidx];
            out[off + BH + p]     = g_h1F[gidx];
            out[off + 2 * BH + p] = g_c0[gidx];
            out[off + 3 * BH + p] = g_c1[gidx];
        }
    }
}

// ---------------- launch ----------------
extern "C" void kernel_launch(void* const* d_in, const int* in_sizes, int n_in,
                              void* d_out, int out_size) {
    const float* x   = (const float*)d_in[0];
    const float* Wi0 = (const float*)d_in[1];
    const float* Wh0 = (const float*)d_in[2];
    const float* bi0 = (const float*)d_in[3];
    const float* bh0 = (const float*)d_in[4];
    const float* Wi1 = (const float*)d_in[5];
    const float* Wh1 = (const float*)d_in[6];
    const float* bi1 = (const float*)d_in[7];
    const float* bh1 = (const float*)d_in[8];
    float* out = (float*)d_out;

    const int smemBytes = (2 * HS_BUF + 2 * WS_BUF + 64 * 65) * 4;  // ~88 KB
    cudaFuncSetAttribute(lstm_persistent,
                         cudaFuncAttributeMaxDynamicSharedMemorySize, smemBytes);

    init_state<<<(H * B + 255) / 256, 256>>>();
    round_weights<<<(G4 * H + 255) / 256, 256>>>(Wh0, Wi1, Wh1);
    precompute_kernel<<<dim3(G4 / 64, (B * T) / 128), 256>>>(x, Wi0, bi0, bh0);
    lstm_persistent<<<NBLK, 256, smemBytes>>>(bi1, bh1, out);
}